// round 13
// baseline (speedup 1.0000x reference)
#include <cuda_runtime.h>

#define HID  128
#define NH   8
#define NSEQ 4096
#define BP   4
#define SROW 4097   // h has 4097 rows per batch; last row is hg
#define FULL 0xffffffffu
#define NSLOT 8

__device__ float g_u[BP*NH*HID];
__device__ float g_wp[NSLOT][BP*NH*HID];   // slot-partitioned UNNORMALIZED sum of e_n*hn
__device__ float g_sump[NSLOT][BP*NH];     // slot-partitioned sum of e_n
__device__ float g_a[BP*NSEQ];
__device__ float g_bv[BP*NSEQ];

__device__ __forceinline__ float wsum(float v) {
    #pragma unroll
    for (int o = 16; o; o >>= 1) v += __shfl_xor_sync(FULL, v, o);
    return v;
}

// 32-dot warp transpose-reduce: lane l ends holding full dot l. 31 shfls.
__device__ __forceinline__ float treduce32(float* p, int lane) {
    #pragma unroll
    for (int off = 16; off; off >>= 1) {
        bool up = (lane & off) != 0;
        #pragma unroll
        for (int k = 0; k < off; k++) {
            float a_ = p[k], b_ = p[k + off];
            float send = up ? a_ : b_;
            float keep = up ? b_ : a_;
            p[k] = keep + __shfl_xor_sync(FULL, send, off);
        }
    }
    return p[0];
}

// ---------------- kA: q = hg@W_q ; u_h = W_k_head@q_h ; zero slot accumulators ----------------
__global__ void kA(const float* __restrict__ h, const float* __restrict__ Wq,
                   const float* __restrict__ Wkv) {
    int b = blockIdx.x, tid = threadIdx.x;           // 512 threads
    #pragma unroll
    for (int s = 0; s < NSLOT; s++) {
        g_wp[s][b*NH*HID + tid]       = 0.f;
        g_wp[s][b*NH*HID + 512 + tid] = 0.f;
        if (tid < NH) g_sump[s][b*NH + tid] = 0.f;
    }

    int t = tid & 127, k = tid >> 7;
    __shared__ float hg[HID], qp[4][HID], qs[HID];
    if (tid < HID) hg[tid] = h[((size_t)b*SROW + NSEQ)*HID + tid];
    __syncthreads();
    float q = 0.f;
    #pragma unroll
    for (int d = k*32; d < k*32 + 32; d++) q += hg[d]*Wq[d*HID + t];
    qp[k][t] = q;
    __syncthreads();
    if (tid < HID) qs[tid] = qp[0][tid] + qp[1][tid] + qp[2][tid] + qp[3][tid];
    __syncthreads();
    #pragma unroll
    for (int it = 0; it < 2; it++) {
        int idx = tid + it*512;
        int hh = idx >> 7, tt = idx & 127;
        float u = 0.f;
        #pragma unroll
        for (int d = 0; d < 16; d++) u += Wkv[tt*256 + hh*16 + d]*qs[hh*16 + d];
        g_u[(b*NH + hh)*HID + tt] = u;
    }
}

// ==== kBC: scores -> exp -> accumulate w, esum  (slot-partitioned atomics) ====
// grid (NSEQ/32, BP) x 256 threads; 8 warps x 4 rows.
__global__ void kBC(const float* __restrict__ h) {
    int b = blockIdx.y, tid = threadIdx.x;
    int warp = tid >> 5, lane = tid & 31;
    int slot = blockIdx.x & (NSLOT-1);
    __shared__ float4 us4[NH][32];
    ((float4*)us4)[tid] = ((const float4*)&g_u[b*NH*HID])[tid];
    __syncthreads();

    int row0 = blockIdx.x*32 + warp*4;
    const float* base = &h[((size_t)b*SROW + row0)*HID];
    float4 r[4];
    #pragma unroll
    for (int i = 0; i < 4; i++)
        r[i] = *(const float4*)&base[(size_t)i*HID + lane*4];

    float p[32];
    #pragma unroll
    for (int hh = 0; hh < NH; hh++) {
        float4 u4 = us4[hh][lane];
        #pragma unroll
        for (int i = 0; i < 4; i++)
            p[hh*4 + i] = r[i].x*u4.x + r[i].y*u4.y + r[i].z*u4.z + r[i].w*u4.w;
    }
    float ev = __expf(0.25f*treduce32(p, lane));   // lane l owns dot l (hh=l>>2, i=l&3)

    float4 acc[NH]; float eh[NH];
    #pragma unroll
    for (int hh = 0; hh < NH; hh++) {
        acc[hh] = make_float4(0.f,0.f,0.f,0.f); eh[hh] = 0.f;
        #pragma unroll
        for (int i = 0; i < 4; i++) {
            float e = __shfl_sync(FULL, ev, hh*4 + i);
            eh[hh] += e;
            acc[hh].x += e*r[i].x; acc[hh].y += e*r[i].y;
            acc[hh].z += e*r[i].z; acc[hh].w += e*r[i].w;
        }
    }
    __shared__ float4 smw[8][NH][32];       // 32KB
    __shared__ float  ses[8][NH];
    #pragma unroll
    for (int hh = 0; hh < NH; hh++) smw[warp][hh][lane] = acc[hh];
    if (lane == 0) {
        #pragma unroll
        for (int hh = 0; hh < NH; hh++) ses[warp][hh] = eh[hh];
    }
    __syncthreads();
    int hh2 = tid >> 5;
    float4 rs = smw[0][hh2][lane];
    #pragma unroll
    for (int s = 1; s < 8; s++) {
        float4 v = smw[s][hh2][lane];
        rs.x += v.x; rs.y += v.y; rs.z += v.z; rs.w += v.w;
    }
    float* dst = &g_wp[slot][(b*NH + hh2)*HID + lane*4];
    atomicAdd(dst+0, rs.x); atomicAdd(dst+1, rs.y);
    atomicAdd(dst+2, rs.z); atomicAdd(dst+3, rs.w);
    if (tid < NH) {
        float s = 0.f;
        #pragma unroll
        for (int w2 = 0; w2 < 8; w2++) s += ses[w2][tid];
        atomicAdd(&g_sump[slot][b*NH + tid], s);
    }
}

// ==== kDE: sum slots; normalize; y = w@W_v; mh = y@W_mhc; y2 = mh.hn; a/bv ====
// grid (NSEQ/128, BP) x 256 threads (8 warps x 16 rows).
__global__ void kDE(const float* __restrict__ h, const float* __restrict__ Wkv,
                    const float* __restrict__ Wmhc, const float* __restrict__ Wlin) {
    int b = blockIdx.y, tid = threadIdx.x;
    int t = tid & 127, k = tid >> 7;                 // k: 0..1
    __shared__ float ws[NH*HID], ys[HID], ms[HID], part[2][HID];
    __shared__ float ssum[NH], w01[2];
    if (tid < NH) {
        float s = 0.f;
        #pragma unroll
        for (int sl = 0; sl < NSLOT; sl++) s += g_sump[sl][b*NH + tid];
        ssum[tid] = s;
    }
    if (tid < 2)  w01[tid]  = Wlin[tid];
    __syncthreads();
    #pragma unroll
    for (int it = 0; it < 4; it++) {
        int i = tid + it*256;
        float v = 0.f;
        #pragma unroll
        for (int sl = 0; sl < NSLOT; sl++) v += g_wp[sl][b*NH*HID + i];
        ws[i] = v / ssum[i >> 7];
    }
    __syncthreads();
    int hh = t >> 4;
    float y = 0.f;
    #pragma unroll
    for (int jj = k*64; jj < k*64 + 64; jj++) y += ws[hh*HID + jj]*Wkv[jj*256 + HID + t];
    part[k][t] = y;
    __syncthreads();
    if (tid < HID) ys[tid] = part[0][tid] + part[1][tid];
    __syncthreads();
    float m = 0.f;
    #pragma unroll
    for (int c = k*64; c < k*64 + 64; c++) m += ys[c]*Wmhc[c*HID + t];
    part[k][t] = m;
    __syncthreads();
    if (tid < HID) ms[tid] = part[0][tid] + part[1][tid];
    __syncthreads();

    int warp = tid >> 5, lane = tid & 31;
    float4 m4 = ((float4*)ms)[lane];
    int row0 = blockIdx.x*128 + warp*16;
    const float* base = &h[((size_t)b*SROW + row0)*HID];
    float out = 0.f;
    #pragma unroll
    for (int i = 0; i < 16; i++) {
        float4 r = *(const float4*)&base[(size_t)i*HID + lane*4];
        float d = r.x*m4.x + r.y*m4.y + r.z*m4.z + r.w*m4.w;
        d = wsum(d);
        if (lane == i) out = d;
    }
    if (lane < 16) {
        g_a [b*NSEQ + row0 + lane] = out*w01[0];
        g_bv[b*NSEQ + row0 + lane] = out*w01[1];
    }
}

// ==== kF: out[b, i*N + j] = a[b,j] + bv[b,i]  (268MB stream) ====
#define ROWS_F 16
__global__ void kF(float* __restrict__ out) {
    int b = blockIdx.y, t = threadIdx.x;                     // 1024 threads
    int i0 = blockIdx.x*ROWS_F;
    float4 a4 = ((const float4*)&g_a[b*NSEQ])[t];
    const float* bv = &g_bv[b*NSEQ];
    float4* ob = (float4*)&out[((size_t)b*NSEQ + i0)*NSEQ];
    #pragma unroll
    for (int r = 0; r < ROWS_F; r++) {
        float bi = bv[i0 + r];
        float4 o4 = make_float4(a4.x+bi, a4.y+bi, a4.z+bi, a4.w+bi);
        __stwt(&ob[(size_t)r*(NSEQ/4) + t], o4);
    }
}

extern "C" void kernel_launch(void* const* d_in, const int* in_sizes, int n_in,
                              void* d_out, int out_size) {
    const float* h    = (const float*)d_in[0];
    const float* Wq   = (const float*)d_in[1];
    const float* Wkv  = (const float*)d_in[2];
    const float* Wmhc = (const float*)d_in[3];
    const float* Wlin = (const float*)d_in[4];
    float* out = (float*)d_out;

    kA  <<<BP, 512>>>(h, Wq, Wkv);
    kBC <<<dim3(NSEQ/32, BP), 256>>>(h);
    kDE <<<dim3(NSEQ/128, BP), 256>>>(h, Wkv, Wmhc, Wlin);
    kF  <<<dim3(NSEQ/ROWS_F, BP), 1024>>>(out);
}

// round 14
// speedup vs baseline: 1.3456x; 1.3456x over previous
#include <cuda_runtime.h>

#define HID  128
#define NH   8
#define NSEQ 4096
#define BP   4
#define SROW 4097   // h has 4097 rows per batch; last row is hg
#define FULL 0xffffffffu

__device__ float g_u[BP*NH*HID];
__device__ float g_w[BP*NH*HID];     // UNNORMALIZED sum of e_n * hn
__device__ float g_sum[BP*NH];       // sum of e_n
__device__ float g_a[BP*NSEQ];
__device__ float g_bv[BP*NSEQ];

__device__ __forceinline__ float wsum(float v) {
    #pragma unroll
    for (int o = 16; o; o >>= 1) v += __shfl_xor_sync(FULL, v, o);
    return v;
}

// 32-dot warp transpose-reduce: lane l ends holding full dot l. 31 shfls.
__device__ __forceinline__ float treduce32(float* p, int lane) {
    #pragma unroll
    for (int off = 16; off; off >>= 1) {
        bool up = (lane & off) != 0;
        #pragma unroll
        for (int k = 0; k < off; k++) {
            float a_ = p[k], b_ = p[k + off];
            float send = up ? a_ : b_;
            float keep = up ? b_ : a_;
            p[k] = keep + __shfl_xor_sync(FULL, send, off);
        }
    }
    return p[0];
}

// ---------------- kA: q = hg@W_q ; u_h = W_k_head@q_h ; zero accumulators ----------------
__global__ void kA(const float* __restrict__ h, const float* __restrict__ Wq,
                   const float* __restrict__ Wkv) {
    int b = blockIdx.x, tid = threadIdx.x;           // 512 threads
    g_w[b*NH*HID + tid]       = 0.f;
    g_w[b*NH*HID + 512 + tid] = 0.f;
    if (tid < NH) g_sum[b*NH + tid] = 0.f;

    int t = tid & 127, k = tid >> 7;
    __shared__ float hg[HID], qp[4][HID], qs[HID];
    if (tid < HID) hg[tid] = h[((size_t)b*SROW + NSEQ)*HID + tid];
    __syncthreads();
    float q = 0.f;
    #pragma unroll
    for (int d = k*32; d < k*32 + 32; d++) q += hg[d]*Wq[d*HID + t];
    qp[k][t] = q;
    __syncthreads();
    if (tid < HID) qs[tid] = qp[0][tid] + qp[1][tid] + qp[2][tid] + qp[3][tid];
    __syncthreads();
    #pragma unroll
    for (int it = 0; it < 2; it++) {
        int idx = tid + it*512;
        int hh = idx >> 7, tt = idx & 127;
        float u = 0.f;
        #pragma unroll
        for (int d = 0; d < 16; d++) u += Wkv[tt*256 + hh*16 + d]*qs[hh*16 + d];
        g_u[(b*NH + hh)*HID + tt] = u;
    }
}

// ==== kBC: scores -> exp -> accumulate w, esum ====
// grid (NSEQ/64, BP) x 256 threads; 8 warps x 8 rows processed as 2 groups of 4
// (register-lean: load -> reduce -> accumulate per group).
__global__ void kBC(const float* __restrict__ h) {
    int b = blockIdx.y, tid = threadIdx.x;
    int warp = tid >> 5, lane = tid & 31;
    __shared__ float4 us4[NH][32];
    ((float4*)us4)[tid] = ((const float4*)&g_u[b*NH*HID])[tid];
    __syncthreads();

    int row0 = blockIdx.x*64 + warp*8;
    const float* base = &h[((size_t)b*SROW + row0)*HID];

    float4 acc[NH]; float eh[NH];
    #pragma unroll
    for (int hh = 0; hh < NH; hh++) { acc[hh] = make_float4(0.f,0.f,0.f,0.f); eh[hh] = 0.f; }

    #pragma unroll
    for (int g = 0; g < 2; g++) {
        float4 r[4];
        #pragma unroll
        for (int i = 0; i < 4; i++)
            r[i] = *(const float4*)&base[(size_t)(g*4 + i)*HID + lane*4];
        float p[32];
        #pragma unroll
        for (int hh = 0; hh < NH; hh++) {
            float4 u4 = us4[hh][lane];
            #pragma unroll
            for (int i = 0; i < 4; i++)
                p[hh*4 + i] = r[i].x*u4.x + r[i].y*u4.y + r[i].z*u4.z + r[i].w*u4.w;
        }
        float ev = __expf(0.25f*treduce32(p, lane));   // lane l owns dot l
        #pragma unroll
        for (int hh = 0; hh < NH; hh++) {
            #pragma unroll
            for (int i = 0; i < 4; i++) {
                float e = __shfl_sync(FULL, ev, hh*4 + i);
                eh[hh] += e;
                acc[hh].x += e*r[i].x; acc[hh].y += e*r[i].y;
                acc[hh].z += e*r[i].z; acc[hh].w += e*r[i].w;
            }
        }
    }

    __shared__ float4 smw[8][NH][32];       // 32KB
    __shared__ float  ses[8][NH];
    #pragma unroll
    for (int hh = 0; hh < NH; hh++) smw[warp][hh][lane] = acc[hh];
    if (lane == 0) {
        #pragma unroll
        for (int hh = 0; hh < NH; hh++) ses[warp][hh] = eh[hh];
    }
    __syncthreads();
    int hh2 = tid >> 5;
    float4 rs = smw[0][hh2][lane];
    #pragma unroll
    for (int s = 1; s < 8; s++) {
        float4 v = smw[s][hh2][lane];
        rs.x += v.x; rs.y += v.y; rs.z += v.z; rs.w += v.w;
    }
    float* dst = &g_w[(b*NH + hh2)*HID + lane*4];
    atomicAdd(dst+0, rs.x); atomicAdd(dst+1, rs.y);
    atomicAdd(dst+2, rs.z); atomicAdd(dst+3, rs.w);
    if (tid < NH) {
        float s = 0.f;
        #pragma unroll
        for (int w2 = 0; w2 < 8; w2++) s += ses[w2][tid];
        atomicAdd(&g_sum[b*NH + tid], s);
    }
}

// ==== kDE: normalize w; y = w@W_v; mh = y@W_mhc; y2 = mh.hn; a/bv ====
// grid (NSEQ/128, BP) x 256 threads (8 warps x 16 rows).
__global__ void kDE(const float* __restrict__ h, const float* __restrict__ Wkv,
                    const float* __restrict__ Wmhc, const float* __restrict__ Wlin) {
    int b = blockIdx.y, tid = threadIdx.x;
    int t = tid & 127, k = tid >> 7;                 // k: 0..1
    __shared__ float ws[NH*HID], ys[HID], ms[HID], part[2][HID];
    __shared__ float ssum[NH], w01[2];
    if (tid < NH) ssum[tid] = g_sum[b*NH + tid];
    if (tid < 2)  w01[tid]  = Wlin[tid];
    __syncthreads();
    #pragma unroll
    for (int it = 0; it < 4; it++) {
        int i = tid + it*256;
        ws[i] = g_w[b*NH*HID + i] / ssum[i >> 7];
    }
    __syncthreads();
    int hh = t >> 4;
    float y = 0.f;
    #pragma unroll
    for (int jj = k*64; jj < k*64 + 64; jj++) y += ws[hh*HID + jj]*Wkv[jj*256 + HID + t];
    part[k][t] = y;
    __syncthreads();
    if (tid < HID) ys[tid] = part[0][tid] + part[1][tid];
    __syncthreads();
    float m = 0.f;
    #pragma unroll
    for (int c = k*64; c < k*64 + 64; c++) m += ys[c]*Wmhc[c*HID + t];
    part[k][t] = m;
    __syncthreads();
    if (tid < HID) ms[tid] = part[0][tid] + part[1][tid];
    __syncthreads();

    int warp = tid >> 5, lane = tid & 31;
    float4 m4 = ((float4*)ms)[lane];
    int row0 = blockIdx.x*128 + warp*16;
    const float* base = &h[((size_t)b*SROW + row0)*HID];
    float out = 0.f;
    #pragma unroll
    for (int i = 0; i < 16; i++) {
        float4 r = *(const float4*)&base[(size_t)i*HID + lane*4];
        float d = r.x*m4.x + r.y*m4.y + r.z*m4.z + r.w*m4.w;
        d = wsum(d);
        if (lane == i) out = d;
    }
    if (lane < 16) {
        g_a [b*NSEQ + row0 + lane] = out*w01[0];
        g_bv[b*NSEQ + row0 + lane] = out*w01[1];
    }
}

// ==== kF: out[b, i*N + j] = a[b,j] + bv[b,i]  (268MB stream) ====
#define ROWS_F 32
__global__ void kF(float* __restrict__ out) {
    int b = blockIdx.y, t = threadIdx.x;                     // 1024 threads
    int i0 = blockIdx.x*ROWS_F;
    float4 a4 = ((const float4*)&g_a[b*NSEQ])[t];
    const float* bv = &g_bv[b*NSEQ];
    float4* ob = (float4*)&out[((size_t)b*NSEQ + i0)*NSEQ];
    #pragma unroll
    for (int r = 0; r < ROWS_F; r++) {
        float bi = bv[i0 + r];
        float4 o4 = make_float4(a4.x+bi, a4.y+bi, a4.z+bi, a4.w+bi);
        __stwt(&ob[(size_t)r*(NSEQ/4) + t], o4);
    }
}

extern "C" void kernel_launch(void* const* d_in, const int* in_sizes, int n_in,
                              void* d_out, int out_size) {
    const float* h    = (const float*)d_in[0];
    const float* Wq   = (const float*)d_in[1];
    const float* Wkv  = (const float*)d_in[2];
    const float* Wmhc = (const float*)d_in[3];
    const float* Wlin = (const float*)d_in[4];
    float* out = (float*)d_out;

    kA  <<<BP, 512>>>(h, Wq, Wkv);
    kBC <<<dim3(NSEQ/64, BP), 256>>>(h);
    kDE <<<dim3(NSEQ/128, BP), 256>>>(h, Wkv, Wmhc, Wlin);
    kF  <<<dim3(NSEQ/ROWS_F, BP), 1024>>>(out);
}

// round 15
// speedup vs baseline: 1.3680x; 1.0166x over previous
#include <cuda_runtime.h>

#define HID  128
#define NH   8
#define NSEQ 4096
#define BP   4
#define SROW 4097   // h has 4097 rows per batch; last row is hg
#define FULL 0xffffffffu

__device__ float g_u[BP*NH*HID];
__device__ float g_w[BP*NH*HID];     // UNNORMALIZED sum of e_n * hn
__device__ float g_sum[BP*NH];       // sum of e_n
__device__ float g_a[BP*NSEQ];
__device__ float g_bv[BP*NSEQ];

__device__ __forceinline__ float wsum(float v) {
    #pragma unroll
    for (int o = 16; o; o >>= 1) v += __shfl_xor_sync(FULL, v, o);
    return v;
}

// 32-dot warp transpose-reduce: lane l ends holding full dot l. 31 shfls.
__device__ __forceinline__ float treduce32(float* p, int lane) {
    #pragma unroll
    for (int off = 16; off; off >>= 1) {
        bool up = (lane & off) != 0;
        #pragma unroll
        for (int k = 0; k < off; k++) {
            float a_ = p[k], b_ = p[k + off];
            float send = up ? a_ : b_;
            float keep = up ? b_ : a_;
            p[k] = keep + __shfl_xor_sync(FULL, send, off);
        }
    }
    return p[0];
}

// ---------------- kA: q = hg@W_q ; u_h = W_k_head@q_h ; zero accumulators ----------------
__global__ void kA(const float* __restrict__ h, const float* __restrict__ Wq,
                   const float* __restrict__ Wkv) {
    int b = blockIdx.x, tid = threadIdx.x;           // 512 threads
    g_w[b*NH*HID + tid]       = 0.f;
    g_w[b*NH*HID + 512 + tid] = 0.f;
    if (tid < NH) g_sum[b*NH + tid] = 0.f;

    int t = tid & 127, k = tid >> 7;
    __shared__ float hg[HID], qp[4][HID], qs[HID];
    if (tid < HID) hg[tid] = h[((size_t)b*SROW + NSEQ)*HID + tid];
    __syncthreads();
    float q = 0.f;
    #pragma unroll
    for (int d = k*32; d < k*32 + 32; d++) q += hg[d]*Wq[d*HID + t];
    qp[k][t] = q;
    __syncthreads();
    if (tid < HID) qs[tid] = qp[0][tid] + qp[1][tid] + qp[2][tid] + qp[3][tid];
    __syncthreads();
    #pragma unroll
    for (int it = 0; it < 2; it++) {
        int idx = tid + it*512;
        int hh = idx >> 7, tt = idx & 127;
        float u = 0.f;
        #pragma unroll
        for (int d = 0; d < 16; d++) u += Wkv[tt*256 + hh*16 + d]*qs[hh*16 + d];
        g_u[(b*NH + hh)*HID + tt] = u;
    }
}

// ==== kBC: scores -> exp -> accumulate w, esum ====
// grid (NSEQ/64, BP) x 256 threads; 8 warps x 8 rows processed as 2 groups of 4
// (register-lean: load -> reduce -> accumulate per group).
__global__ void kBC(const float* __restrict__ h) {
    int b = blockIdx.y, tid = threadIdx.x;
    int warp = tid >> 5, lane = tid & 31;
    __shared__ float4 us4[NH][32];
    ((float4*)us4)[tid] = ((const float4*)&g_u[b*NH*HID])[tid];
    __syncthreads();

    int row0 = blockIdx.x*64 + warp*8;
    const float* base = &h[((size_t)b*SROW + row0)*HID];

    float4 acc[NH]; float eh[NH];
    #pragma unroll
    for (int hh = 0; hh < NH; hh++) { acc[hh] = make_float4(0.f,0.f,0.f,0.f); eh[hh] = 0.f; }

    #pragma unroll
    for (int g = 0; g < 2; g++) {
        float4 r[4];
        #pragma unroll
        for (int i = 0; i < 4; i++)
            r[i] = *(const float4*)&base[(size_t)(g*4 + i)*HID + lane*4];
        float p[32];
        #pragma unroll
        for (int hh = 0; hh < NH; hh++) {
            float4 u4 = us4[hh][lane];
            #pragma unroll
            for (int i = 0; i < 4; i++)
                p[hh*4 + i] = r[i].x*u4.x + r[i].y*u4.y + r[i].z*u4.z + r[i].w*u4.w;
        }
        float ev = __expf(0.25f*treduce32(p, lane));   // lane l owns dot l
        #pragma unroll
        for (int hh = 0; hh < NH; hh++) {
            #pragma unroll
            for (int i = 0; i < 4; i++) {
                float e = __shfl_sync(FULL, ev, hh*4 + i);
                eh[hh] += e;
                acc[hh].x += e*r[i].x; acc[hh].y += e*r[i].y;
                acc[hh].z += e*r[i].z; acc[hh].w += e*r[i].w;
            }
        }
    }

    __shared__ float4 smw[8][NH][32];       // 32KB
    __shared__ float  ses[8][NH];
    #pragma unroll
    for (int hh = 0; hh < NH; hh++) smw[warp][hh][lane] = acc[hh];
    if (lane == 0) {
        #pragma unroll
        for (int hh = 0; hh < NH; hh++) ses[warp][hh] = eh[hh];
    }
    __syncthreads();
    int hh2 = tid >> 5;
    float4 rs = smw[0][hh2][lane];
    #pragma unroll
    for (int s = 1; s < 8; s++) {
        float4 v = smw[s][hh2][lane];
        rs.x += v.x; rs.y += v.y; rs.z += v.z; rs.w += v.w;
    }
    float* dst = &g_w[(b*NH + hh2)*HID + lane*4];
    atomicAdd(dst+0, rs.x); atomicAdd(dst+1, rs.y);
    atomicAdd(dst+2, rs.z); atomicAdd(dst+3, rs.w);
    if (tid < NH) {
        float s = 0.f;
        #pragma unroll
        for (int w2 = 0; w2 < 8; w2++) s += ses[w2][tid];
        atomicAdd(&g_sum[b*NH + tid], s);
    }
}

// ==== kDE: normalize w; y = w@W_v; mh = y@W_mhc; y2 = mh.hn; a/bv ====
// grid (NSEQ/128, BP) x 256 threads (8 warps x 16 rows).
__global__ void kDE(const float* __restrict__ h, const float* __restrict__ Wkv,
                    const float* __restrict__ Wmhc, const float* __restrict__ Wlin) {
    int b = blockIdx.y, tid = threadIdx.x;
    int t = tid & 127, k = tid >> 7;                 // k: 0..1
    __shared__ float ws[NH*HID], ys[HID], ms[HID], part[2][HID];
    __shared__ float ssum[NH], w01[2];
    if (tid < NH) ssum[tid] = g_sum[b*NH + tid];
    if (tid < 2)  w01[tid]  = Wlin[tid];
    __syncthreads();
    #pragma unroll
    for (int it = 0; it < 4; it++) {
        int i = tid + it*256;
        ws[i] = g_w[b*NH*HID + i] / ssum[i >> 7];
    }
    __syncthreads();
    int hh = t >> 4;
    float y = 0.f;
    #pragma unroll
    for (int jj = k*64; jj < k*64 + 64; jj++) y += ws[hh*HID + jj]*Wkv[jj*256 + HID + t];
    part[k][t] = y;
    __syncthreads();
    if (tid < HID) ys[tid] = part[0][tid] + part[1][tid];
    __syncthreads();
    float m = 0.f;
    #pragma unroll
    for (int c = k*64; c < k*64 + 64; c++) m += ys[c]*Wmhc[c*HID + t];
    part[k][t] = m;
    __syncthreads();
    if (tid < HID) ms[tid] = part[0][tid] + part[1][tid];
    __syncthreads();

    int warp = tid >> 5, lane = tid & 31;
    float4 m4 = ((float4*)ms)[lane];
    int row0 = blockIdx.x*128 + warp*16;
    const float* base = &h[((size_t)b*SROW + row0)*HID];
    float out = 0.f;
    #pragma unroll
    for (int i = 0; i < 16; i++) {
        float4 r = *(const float4*)&base[(size_t)i*HID + lane*4];
        float d = r.x*m4.x + r.y*m4.y + r.z*m4.z + r.w*m4.w;
        d = wsum(d);
        if (lane == i) out = d;
    }
    if (lane < 16) {
        g_a [b*NSEQ + row0 + lane] = out*w01[0];
        g_bv[b*NSEQ + row0 + lane] = out*w01[1];
    }
}

// ==== kF: out[b, i*N + j] = a[b,j] + bv[b,i]  (268MB stream) ====
#define ROWS_F 16
__global__ void kF(float* __restrict__ out) {
    int b = blockIdx.y, t = threadIdx.x;                     // 1024 threads
    int i0 = blockIdx.x*ROWS_F;
    float4 a4 = ((const float4*)&g_a[b*NSEQ])[t];
    const float* bv = &g_bv[b*NSEQ];
    float4* ob = (float4*)&out[((size_t)b*NSEQ + i0)*NSEQ];
    #pragma unroll
    for (int r = 0; r < ROWS_F; r++) {
        float bi = bv[i0 + r];
        float4 o4 = make_float4(a4.x+bi, a4.y+bi, a4.z+bi, a4.w+bi);
        __stwt(&ob[(size_t)r*(NSEQ/4) + t], o4);
    }
}

extern "C" void kernel_launch(void* const* d_in, const int* in_sizes, int n_in,
                              void* d_out, int out_size) {
    const float* h    = (const float*)d_in[0];
    const float* Wq   = (const float*)d_in[1];
    const float* Wkv  = (const float*)d_in[2];
    const float* Wmhc = (const float*)d_in[3];
    const float* Wlin = (const float*)d_in[4];
    float* out = (float*)d_out;

    kA  <<<BP, 512>>>(h, Wq, Wkv);
    kBC <<<dim3(NSEQ/64, BP), 256>>>(h);
    kDE <<<dim3(NSEQ/128, BP), 256>>>(h, Wkv, Wmhc, Wlin);
    kF  <<<dim3(NSEQ/ROWS_F, BP), 1024>>>(out);
}